// round 3
// baseline (speedup 1.0000x reference)
#include <cuda_runtime.h>

// ---------------- static config ----------------
namespace cfg {
constexpr int NN = 10000;       // nodes
constexpr int NE = 128000;      // edges
constexpr int NS = 16;
constexpr int NWARP = 12;       // warps per conv block
constexpr int CONV_THREADS = NWARP * 32;
constexpr int WS = 572;         // per-warp scratch floats
// smem: W1(48*64) + B1(64) + W2(64*416) + B2(416) + warp scratch
constexpr int SMEM_FLOATS = 48*64 + 64 + 64*416 + 416 + NWARP*WS;
constexpr int SMEM_BYTES = SMEM_FLOATS * 4;   // 148160
}

// ---------------- device scratch (no allocations allowed) ----------------
__device__ float g_h0[cfg::NN * 16];
__device__ float g_h1[cfg::NN * 12];
__device__ float g_acc0[cfg::NN * 16];
__device__ float g_acc1[cfg::NN * 12];
__device__ float g_cnt[cfg::NN];
__device__ float g_eattr[cfg::NE * 16];
__device__ float g_y1[cfg::NE * 3];

// ---------------- zero scratch ----------------
__global__ void zero_kernel() {
    int i = blockIdx.x * blockDim.x + threadIdx.x;
    int stride = gridDim.x * blockDim.x;
    for (int t = i; t < cfg::NN * 16; t += stride) g_acc0[t] = 0.f;
    for (int t = i; t < cfg::NN * 12; t += stride) { g_acc1[t] = 0.f; g_h1[t] = 0.f; }
    for (int t = i; t < cfg::NN; t += stride) g_cnt[t] = 0.f;
}

// ---------------- node encoder + node_embedding MLP ----------------
__global__ void node_init_kernel(const float* __restrict__ nf,
                                 const float* __restrict__ encW, const float* __restrict__ encB,
                                 const float* __restrict__ W1, const float* __restrict__ B1,
                                 const float* __restrict__ W2, const float* __restrict__ B2) {
    int n = blockIdx.x * blockDim.x + threadIdx.x;
    if (n >= cfg::NN) return;
    float enc[16];
    #pragma unroll
    for (int c = 0; c < 16; c++) enc[c] = encB[c];
    for (int f = 0; f < 64; f++) {
        float v = nf[n * 64 + f];
        #pragma unroll
        for (int c = 0; c < 16; c++) enc[c] = fmaf(v, encW[f * 16 + c], enc[c]);
    }
    float t[16];
    #pragma unroll
    for (int c = 0; c < 16; c++) {
        float a = B1[c];
        #pragma unroll
        for (int j = 0; j < 16; j++) a = fmaf(enc[j], W1[j * 16 + c], a);
        t[c] = fmaxf(a, 0.f);
    }
    #pragma unroll
    for (int c = 0; c < 16; c++) {
        float a = B2[c];
        #pragma unroll
        for (int j = 0; j < 16; j++) a = fmaf(t[j], W2[j * 16 + c], a);
        g_h0[n * 16 + c] = a;
    }
}

// ---------------- per-edge: geometry, rbf, edge_attr, degree count ----------------
__global__ void edge_init_kernel(const float* __restrict__ pos,
                                 const float* __restrict__ eain, const int* __restrict__ ei,
                                 const float* __restrict__ eeW1, const float* __restrict__ eeB1,
                                 const float* __restrict__ eeW2, const float* __restrict__ eeB2,
                                 const float* __restrict__ reW1, const float* __restrict__ reB1,
                                 const float* __restrict__ reW2, const float* __restrict__ reB2) {
    int e = blockIdx.x * blockDim.x + threadIdx.x;
    if (e >= cfg::NE) return;
    int sn = ei[e], dn = ei[cfg::NE + e];
    float vx = pos[sn * 3 + 0] - pos[dn * 3 + 0];
    float vy = pos[sn * 3 + 1] - pos[dn * 3 + 1];
    float vz = pos[sn * 3 + 2] - pos[dn * 3 + 2];
    float d = sqrtf(vx * vx + vy * vy + vz * vz);
    float dmx = fmaxf(d, 1e-9f);
    float s = 1.7320508075688772f / dmx;     // sqrt(3) * unit
    g_y1[e * 3 + 0] = s * vx;
    g_y1[e * 3 + 1] = s * vy;
    g_y1[e * 3 + 2] = s * vz;
    atomicAdd(&g_cnt[sn], 1.f);

    // edge_embedding MLP on raw edge attrs
    float xin[16];
    #pragma unroll
    for (int j = 0; j < 16; j++) xin[j] = eain[e * 16 + j];
    float he[16];
    #pragma unroll
    for (int c = 0; c < 16; c++) {
        float a = eeB1[c];
        #pragma unroll
        for (int j = 0; j < 16; j++) a = fmaf(xin[j], eeW1[j * 16 + c], a);
        he[c] = fmaxf(a, 0.f);
    }
    // Gaussian smearing + radius_embedding hidden (fused, rbf never stored)
    const float step = 12.0f / 31.0f;
    const float coeff = -0.5f / (step * step);
    float hr[16];
    #pragma unroll
    for (int c = 0; c < 16; c++) hr[c] = reB1[c];
    #pragma unroll 4
    for (int r = 0; r < 32; r++) {
        float t = d - (float)r * step;
        float rb = __expf(coeff * t * t);
        #pragma unroll
        for (int c = 0; c < 16; c++) hr[c] = fmaf(rb, reW1[r * 16 + c], hr[c]);
    }
    #pragma unroll
    for (int c = 0; c < 16; c++) hr[c] = fmaxf(hr[c], 0.f);
    // output layers of both MLPs summed
    #pragma unroll
    for (int c = 0; c < 16; c++) {
        float a = eeB2[c] + reB2[c];
        #pragma unroll
        for (int j = 0; j < 16; j++)
            a = fmaf(he[j], eeW2[j * 16 + c], fmaf(hr[j], reW2[j * 16 + c], a));
        g_eattr[e * 16 + c] = a;
    }
}

// ---------------- conv layer: per-edge weight MLP + tensor product + scatter ----------------
__global__ void __launch_bounds__(cfg::CONV_THREADS, 1)
conv_kernel(const int* __restrict__ ei,
            const float* __restrict__ W1g, const float* __restrict__ B1g,
            const float* __restrict__ W2g, const float* __restrict__ B2g) {
    extern __shared__ float smem[];
    float* sW1 = smem;               // [48][64]
    float* sB1 = sW1 + 3072;         // [64]
    float* sW2 = sB1 + 64;           // [64][416]
    float* sB2 = sW2 + 26624;        // [416]
    float* sWS = sB2 + 416;

    for (int t = threadIdx.x; t < 3072; t += blockDim.x) sW1[t] = W1g[t];
    for (int t = threadIdx.x; t < 64; t += blockDim.x) sB1[t] = B1g[t];
    for (int t = threadIdx.x; t < 26624; t += blockDim.x) sW2[t] = W2g[t];
    for (int t = threadIdx.x; t < 416; t += blockDim.x) sB2[t] = B2g[t];
    __syncthreads();

    const int lane = threadIdx.x & 31;
    const int warp = threadIdx.x >> 5;
    float* ws   = sWS + warp * cfg::WS;
    float* s_ea  = ws;          // [4][48] : [edge_attr | h0[src] | h0[dst]]
    float* s_h   = ws + 192;    // [4][64] : fc1 hidden
    float* s_x1  = ws + 448;    // [4][4][3]
    float* s_y1  = ws + 496;    // [4][3]
    float* s_dot = ws + 508;    // [4][4]  (x1.y1)/sqrt3
    float* s_cr  = ws + 524;    // [4][4][3] cross(x1,y1)/sqrt2

    const unsigned FULL = 0xffffffffu;
    const int numGroups = cfg::NE / 4;
    const int warpsTotal = gridDim.x * cfg::NWARP;

    for (int g = blockIdx.x * cfg::NWARP + warp; g < numGroups; g += warpsTotal) {
        const int ebase = g * 4;

        // ---- phase 1: gather edge features (4 edges) ----
        #pragma unroll
        for (int j = 0; j < 6; j++) {
            int t = lane + 32 * j;          // 0..191
            int e = t / 48;
            int c = t - e * 48;
            int edge = ebase + e;
            float v;
            if (c < 16) {
                v = g_eattr[edge * 16 + c];
            } else if (c < 32) {
                int sn = ei[edge];
                v = g_h0[sn * 16 + (c - 16)];
            } else {
                int dn = ei[cfg::NE + edge];
                v = g_h0[dn * 16 + (c - 32)];
            }
            s_ea[t] = v;
        }
        if (lane < 12) {
            int e = lane / 3, m = lane - e * 3;
            s_y1[lane] = g_y1[(ebase + e) * 3 + m];
        }
        if (lane < 16) {
            int e = lane >> 2, n = lane & 3;
            int dn = ei[cfg::NE + ebase + e];
            s_x1[e * 12 + n * 3 + 0] = g_h1[dn * 12 + n * 3 + 0];
            s_x1[e * 12 + n * 3 + 1] = g_h1[dn * 12 + n * 3 + 1];
            s_x1[e * 12 + n * 3 + 2] = g_h1[dn * 12 + n * 3 + 2];
        }
        __syncwarp();
        if (lane < 16) {
            int e = lane >> 2, n = lane & 3;
            float xa = s_x1[e * 12 + n * 3 + 0], xb = s_x1[e * 12 + n * 3 + 1], xc = s_x1[e * 12 + n * 3 + 2];
            float ya = s_y1[e * 3 + 0], yb = s_y1[e * 3 + 1], yc = s_y1[e * 3 + 2];
            s_dot[e * 4 + n] = (xa * ya + xb * yb + xc * yc) * 0.57735026918962576f;
            s_cr[e * 12 + n * 3 + 0] = (xb * yc - xc * yb) * 0.70710678118654752f;
            s_cr[e * 12 + n * 3 + 1] = (xc * ya - xa * yc) * 0.70710678118654752f;
            s_cr[e * 12 + n * 3 + 2] = (xa * yb - xb * ya) * 0.70710678118654752f;
        }
        __syncwarp();

        // ---- phase 2: fc1 (48 -> 64, relu). lane owns hidden k = lane, lane+32 ----
        float ha[8];
        #pragma unroll
        for (int e = 0; e < 4; e++) { ha[e * 2] = sB1[lane]; ha[e * 2 + 1] = sB1[lane + 32]; }
        #pragma unroll 4
        for (int c = 0; c < 48; c++) {
            float w1a = sW1[c * 64 + lane];
            float w1b = sW1[c * 64 + lane + 32];
            #pragma unroll
            for (int e = 0; e < 4; e++) {
                float v = s_ea[e * 48 + c];
                ha[e * 2]     = fmaf(v, w1a, ha[e * 2]);
                ha[e * 2 + 1] = fmaf(v, w1b, ha[e * 2 + 1]);
            }
        }
        #pragma unroll
        for (int e = 0; e < 4; e++) {
            s_h[e * 64 + lane]      = fmaxf(ha[e * 2], 0.f);
            s_h[e * 64 + lane + 32] = fmaxf(ha[e * 2 + 1], 0.f);
        }
        __syncwarp();

        // ---- phase 3: fc2 (64 -> 416). lane owns p = lane + 32*i, i=0..12 ----
        float wa[4][13];
        #pragma unroll
        for (int i = 0; i < 13; i++) {
            float b = sB2[lane + 32 * i];
            wa[0][i] = b; wa[1][i] = b; wa[2][i] = b; wa[3][i] = b;
        }
        #pragma unroll 2
        for (int k = 0; k < 64; k++) {
            float h0v = s_h[k], h1v = s_h[64 + k], h2v = s_h[128 + k], h3v = s_h[192 + k];
            const float* r = sW2 + k * 416 + lane;
            #pragma unroll
            for (int i = 0; i < 13; i++) {
                float w2v = r[32 * i];
                wa[0][i] = fmaf(h0v, w2v, wa[0][i]);
                wa[1][i] = fmaf(h1v, w2v, wa[1][i]);
                wa[2][i] = fmaf(h2v, w2v, wa[2][i]);
                wa[3][i] = fmaf(h3v, w2v, wa[3][i]);
            }
        }

        // ---- phase 4: tensor-product contraction via shuffle reductions + scatter ----
        // w layout: [0,256)=w00[n16,o16] [256,320)=w011[n16,o4] [320,336)=w101[n4,o4]
        //           [336,400)=w110[n4,o16] [400,416)=w111[n4,o4]
        #pragma unroll
        for (int e = 0; e < 4; e++) {
            const float* x0p = s_ea + e * 48 + 32;   // h0[dst]
            float ro0 = 0.f, rt = 0.f, r1a = 0.f, r1b = 0.f, r1c = 0.f;
            // w00: i=0..7, n = 2i + lane/16, o = lane&15; pairwise xor16 reduce
            #pragma unroll
            for (int i = 0; i < 8; i++) {
                int n = 2 * i + (lane >> 4);
                float c = wa[e][i] * x0p[n];
                ro0 += c + __shfl_xor_sync(FULL, c, 16);
            }
            // w011: i=8,9 -> t011[o = lane&3] via xor4/8/16
            #pragma unroll
            for (int i = 8; i < 10; i++) {
                int n = ((i - 8) * 32 + lane) >> 2;
                float c = wa[e][i] * x0p[n];
                c += __shfl_xor_sync(FULL, c, 4);
                c += __shfl_xor_sync(FULL, c, 8);
                c += __shfl_xor_sync(FULL, c, 16);
                rt += c;
            }
            {   // i=10: low lanes w101 (n=lane/4,o=lane&3), high lanes w110 (n=0,o=lane-16)
                float w = wa[e][10];
                float c = (lane >= 16) ? w * s_dot[e * 4 + 0] : 0.f;
                ro0 += c + __shfl_xor_sync(FULL, c, 16);
                int n = (lane & 15) >> 2;
                const float* xp = s_x1 + e * 12 + n * 3;
                float m0 = (lane < 16) ? w * xp[0] : 0.f;
                float m1 = (lane < 16) ? w * xp[1] : 0.f;
                float m2 = (lane < 16) ? w * xp[2] : 0.f;
                m0 += __shfl_xor_sync(FULL, m0, 4); m0 += __shfl_xor_sync(FULL, m0, 8);
                m1 += __shfl_xor_sync(FULL, m1, 4); m1 += __shfl_xor_sync(FULL, m1, 8);
                m2 += __shfl_xor_sync(FULL, m2, 4); m2 += __shfl_xor_sync(FULL, m2, 8);
                r1a += m0; r1b += m1; r1c += m2;
            }
            {   // i=11: all w110, n = 1 (low) / 2 (high), o = lane&15
                float c = wa[e][11] * s_dot[e * 4 + ((lane < 16) ? 1 : 2)];
                ro0 += c + __shfl_xor_sync(FULL, c, 16);
            }
            {   // i=12: low lanes w110 (n=3,o=lane), high lanes w111 (n=(lane-16)/4,o=(lane-16)&3)
                float w = wa[e][12];
                float c = (lane < 16) ? w * s_dot[e * 4 + 3] : 0.f;
                ro0 += c + __shfl_xor_sync(FULL, c, 16);
                int n = (lane & 15) >> 2;
                const float* cp = s_cr + e * 12 + n * 3;
                float m0 = (lane >= 16) ? w * cp[0] : 0.f;
                float m1 = (lane >= 16) ? w * cp[1] : 0.f;
                float m2 = (lane >= 16) ? w * cp[2] : 0.f;
                m0 += __shfl_xor_sync(FULL, m0, 4); m0 += __shfl_xor_sync(FULL, m0, 8); m0 += __shfl_xor_sync(FULL, m0, 16);
                m1 += __shfl_xor_sync(FULL, m1, 4); m1 += __shfl_xor_sync(FULL, m1, 8); m1 += __shfl_xor_sync(FULL, m1, 16);
                m2 += __shfl_xor_sync(FULL, m2, 4); m2 += __shfl_xor_sync(FULL, m2, 8); m2 += __shfl_xor_sync(FULL, m2, 16);
                r1a += m0; r1b += m1; r1c += m2;
            }
            // t011[o] * y1[m]  (rt holds t011[lane&3] on every lane)
            r1a += rt * s_y1[e * 3 + 0];
            r1b += rt * s_y1[e * 3 + 1];
            r1c += rt * s_y1[e * 3 + 2];

            int sn = ei[ebase + e];
            if (lane < 16)
                atomicAdd(&g_acc0[sn * 16 + lane], 0.22360679774997896f * ro0);   // 1/sqrt(20)
            if (lane < 4) {
                atomicAdd(&g_acc1[sn * 12 + lane * 3 + 0], 0.20412414523193150f * r1a); // 1/sqrt(24)
                atomicAdd(&g_acc1[sn * 12 + lane * 3 + 1], 0.20412414523193150f * r1b);
                atomicAdd(&g_acc1[sn * 12 + lane * 3 + 2], 0.20412414523193150f * r1c);
            }
        }
        __syncwarp();
    }
}

// ---------------- scatter-mean residual update, zero accumulators ----------------
__global__ void update_kernel() {
    int i = blockIdx.x * blockDim.x + threadIdx.x;
    if (i < cfg::NN * 16) {
        int n = i >> 4;
        float inv = 1.f / fmaxf(g_cnt[n], 1.f);
        g_h0[i] += g_acc0[i] * inv;
        g_acc0[i] = 0.f;
    }
    if (i < cfg::NN * 12) {
        int n = i / 12;
        float inv = 1.f / fmaxf(g_cnt[n], 1.f);
        g_h1[i] += g_acc1[i] * inv;
        g_acc1[i] = 0.f;
    }
}

// ---------------- final update + o3.Linear + sorter layout ----------------
__global__ void final_kernel(float* __restrict__ out,
                             const float* __restrict__ lin0, const float* __restrict__ lin1) {
    int n = blockIdx.x * blockDim.x + threadIdx.x;
    if (n >= cfg::NN) return;
    float inv = 1.f / fmaxf(g_cnt[n], 1.f);
    float h0f[16];
    #pragma unroll
    for (int s = 0; s < 16; s++) h0f[s] = g_h0[n * 16 + s] + g_acc0[n * 16 + s] * inv;
    float h1f[12];
    #pragma unroll
    for (int s = 0; s < 12; s++) h1f[s] = g_h1[n * 12 + s] + g_acc1[n * 12 + s] * inv;
    float* o = out + (size_t)n * 128;
    #pragma unroll 4
    for (int c = 0; c < 32; c++) {
        float f0 = 0.f;
        #pragma unroll
        for (int s = 0; s < 16; s++) f0 = fmaf(h0f[s], lin0[s * 32 + c], f0);
        o[4 * c] = 0.25f * f0;                 // 1/sqrt(16)
        #pragma unroll
        for (int m = 0; m < 3; m++) {
            float f1 = 0.f;
            #pragma unroll
            for (int v = 0; v < 4; v++) f1 = fmaf(h1f[v * 3 + m], lin1[v * 32 + c], f1);
            o[4 * c + 1 + m] = 0.5f * f1;      // 1/sqrt(4)
        }
    }
}

// ---------------- launch ----------------
extern "C" void kernel_launch(void* const* d_in, const int* in_sizes, int n_in,
                              void* d_out, int out_size) {
    const float* pos          = (const float*)d_in[0];
    const float* node_feats   = (const float*)d_in[1];
    const float* edge_attr_in = (const float*)d_in[2];
    const int*   edge_index   = (const int*)d_in[3];
    const float* enc_W  = (const float*)d_in[4];
    const float* enc_b  = (const float*)d_in[5];
    const float* ne_W1  = (const float*)d_in[6];
    const float* ne_b1  = (const float*)d_in[7];
    const float* ne_W2  = (const float*)d_in[8];
    const float* ne_b2  = (const float*)d_in[9];
    const float* ee_W1  = (const float*)d_in[10];
    const float* ee_b1  = (const float*)d_in[11];
    const float* ee_W2  = (const float*)d_in[12];
    const float* ee_b2  = (const float*)d_in[13];
    const float* re_W1  = (const float*)d_in[14];
    const float* re_b1  = (const float*)d_in[15];
    const float* re_W2  = (const float*)d_in[16];
    const float* re_b2  = (const float*)d_in[17];
    const float* fc1_W  = (const float*)d_in[18];   // [2,48,64]
    const float* fc1_b  = (const float*)d_in[19];   // [2,64]
    const float* fc2_W  = (const float*)d_in[20];   // [2,64,416]
    const float* fc2_b  = (const float*)d_in[21];   // [2,416]
    const float* lin0_W = (const float*)d_in[22];
    const float* lin1_W = (const float*)d_in[23];
    float* out = (float*)d_out;

    int dev = 0;
    cudaGetDevice(&dev);
    int nsm = 148;
    cudaDeviceGetAttribute(&nsm, cudaDevAttrMultiProcessorCount, dev);
    cudaFuncSetAttribute(conv_kernel, cudaFuncAttributeMaxDynamicSharedMemorySize, cfg::SMEM_BYTES);

    zero_kernel<<<256, 256>>>();
    node_init_kernel<<<(cfg::NN + 127) / 128, 128>>>(node_feats, enc_W, enc_b,
                                                     ne_W1, ne_b1, ne_W2, ne_b2);
    edge_init_kernel<<<(cfg::NE + 127) / 128, 128>>>(pos, edge_attr_in, edge_index,
                                                     ee_W1, ee_b1, ee_W2, ee_b2,
                                                     re_W1, re_b1, re_W2, re_b2);
    // layer 0
    conv_kernel<<<nsm, cfg::CONV_THREADS, cfg::SMEM_BYTES>>>(edge_index,
        fc1_W, fc1_b, fc2_W, fc2_b);
    update_kernel<<<(cfg::NN * 16 + 255) / 256, 256>>>();
    // layer 1
    conv_kernel<<<nsm, cfg::CONV_THREADS, cfg::SMEM_BYTES>>>(edge_index,
        fc1_W + 48 * 64, fc1_b + 64, fc2_W + 64 * 416, fc2_b + 416);
    // final update + output projection
    final_kernel<<<(cfg::NN + 127) / 128, 128>>>(out, lin0_W, lin1_W);
}

// round 4
// speedup vs baseline: 1.2585x; 1.2585x over previous
#include <cuda_runtime.h>

// ---------------- static config ----------------
namespace cfg {
constexpr int NN = 10000;       // nodes
constexpr int NE = 128000;      // edges
constexpr int NWARP = 12;       // warps per conv block
constexpr int CONV_THREADS = NWARP * 32;
constexpr int EPG = 8;          // edges per warp-group
constexpr int WS = 1160;        // per-warp scratch floats (even -> 8B alignment holds)
// smem: W1(48*64) + B1(64) + W2(64*416 permuted) + B2(416) + warp scratch
constexpr int SMEM_FLOATS = 48*64 + 64 + 64*416 + 416 + NWARP*WS;
constexpr int SMEM_BYTES = SMEM_FLOATS * 4;   // 176384
}

typedef unsigned long long ull;

__device__ __forceinline__ ull pk2(float lo, float hi) {
    ull r; asm("mov.b64 %0, {%1,%2};" : "=l"(r) : "f"(lo), "f"(hi)); return r;
}
__device__ __forceinline__ float2 upk2(ull v) {
    float2 f; asm("mov.b64 {%0,%1}, %2;" : "=f"(f.x), "=f"(f.y) : "l"(v)); return f;
}
__device__ __forceinline__ ull ffma2(ull a, ull b, ull c) {
    ull d; asm("fma.rn.f32x2 %0, %1, %2, %3;" : "=l"(d) : "l"(a), "l"(b), "l"(c)); return d;
}

// ---------------- device scratch (no allocations allowed) ----------------
__device__ float g_h0[cfg::NN * 16];
__device__ float g_h1[cfg::NN * 12];
__device__ float g_acc0[cfg::NN * 16];
__device__ float g_acc1[cfg::NN * 12];
__device__ float g_cnt[cfg::NN];
__device__ float g_eattr[cfg::NE * 16];
__device__ float g_y1[cfg::NE * 3];

// ---------------- zero scratch ----------------
__global__ void zero_kernel() {
    int i = blockIdx.x * blockDim.x + threadIdx.x;
    int stride = gridDim.x * blockDim.x;
    for (int t = i; t < cfg::NN * 16; t += stride) g_acc0[t] = 0.f;
    for (int t = i; t < cfg::NN * 12; t += stride) { g_acc1[t] = 0.f; g_h1[t] = 0.f; }
    for (int t = i; t < cfg::NN; t += stride) g_cnt[t] = 0.f;
}

// ---------------- node encoder + node_embedding MLP ----------------
__global__ void node_init_kernel(const float* __restrict__ nf,
                                 const float* __restrict__ encW, const float* __restrict__ encB,
                                 const float* __restrict__ W1, const float* __restrict__ B1,
                                 const float* __restrict__ W2, const float* __restrict__ B2) {
    int n = blockIdx.x * blockDim.x + threadIdx.x;
    if (n >= cfg::NN) return;
    float enc[16];
    #pragma unroll
    for (int c = 0; c < 16; c++) enc[c] = encB[c];
    for (int f = 0; f < 64; f++) {
        float v = nf[n * 64 + f];
        #pragma unroll
        for (int c = 0; c < 16; c++) enc[c] = fmaf(v, encW[f * 16 + c], enc[c]);
    }
    float t[16];
    #pragma unroll
    for (int c = 0; c < 16; c++) {
        float a = B1[c];
        #pragma unroll
        for (int j = 0; j < 16; j++) a = fmaf(enc[j], W1[j * 16 + c], a);
        t[c] = fmaxf(a, 0.f);
    }
    #pragma unroll
    for (int c = 0; c < 16; c++) {
        float a = B2[c];
        #pragma unroll
        for (int j = 0; j < 16; j++) a = fmaf(t[j], W2[j * 16 + c], a);
        g_h0[n * 16 + c] = a;
    }
}

// ---------------- per-edge: geometry, rbf, edge_attr, degree count ----------------
__global__ void edge_init_kernel(const float* __restrict__ pos,
                                 const float* __restrict__ eain, const int* __restrict__ ei,
                                 const float* __restrict__ eeW1, const float* __restrict__ eeB1,
                                 const float* __restrict__ eeW2, const float* __restrict__ eeB2,
                                 const float* __restrict__ reW1, const float* __restrict__ reB1,
                                 const float* __restrict__ reW2, const float* __restrict__ reB2) {
    int e = blockIdx.x * blockDim.x + threadIdx.x;
    if (e >= cfg::NE) return;
    int sn = ei[e], dn = ei[cfg::NE + e];
    float vx = pos[sn * 3 + 0] - pos[dn * 3 + 0];
    float vy = pos[sn * 3 + 1] - pos[dn * 3 + 1];
    float vz = pos[sn * 3 + 2] - pos[dn * 3 + 2];
    float d = sqrtf(vx * vx + vy * vy + vz * vz);
    float dmx = fmaxf(d, 1e-9f);
    float s = 1.7320508075688772f / dmx;     // sqrt(3) * unit
    g_y1[e * 3 + 0] = s * vx;
    g_y1[e * 3 + 1] = s * vy;
    g_y1[e * 3 + 2] = s * vz;
    atomicAdd(&g_cnt[sn], 1.f);

    // edge_embedding MLP on raw edge attrs
    float xin[16];
    #pragma unroll
    for (int j = 0; j < 16; j++) xin[j] = eain[e * 16 + j];
    float he[16];
    #pragma unroll
    for (int c = 0; c < 16; c++) {
        float a = eeB1[c];
        #pragma unroll
        for (int j = 0; j < 16; j++) a = fmaf(xin[j], eeW1[j * 16 + c], a);
        he[c] = fmaxf(a, 0.f);
    }
    // Gaussian smearing + radius_embedding hidden (fused, rbf never stored)
    const float step = 12.0f / 31.0f;
    const float coeff = -0.5f / (step * step);
    float hr[16];
    #pragma unroll
    for (int c = 0; c < 16; c++) hr[c] = reB1[c];
    #pragma unroll 4
    for (int r = 0; r < 32; r++) {
        float t = d - (float)r * step;
        float rb = __expf(coeff * t * t);
        #pragma unroll
        for (int c = 0; c < 16; c++) hr[c] = fmaf(rb, reW1[r * 16 + c], hr[c]);
    }
    #pragma unroll
    for (int c = 0; c < 16; c++) hr[c] = fmaxf(hr[c], 0.f);
    // output layers of both MLPs summed
    #pragma unroll
    for (int c = 0; c < 16; c++) {
        float a = eeB2[c] + reB2[c];
        #pragma unroll
        for (int j = 0; j < 16; j++)
            a = fmaf(he[j], eeW2[j * 16 + c], fmaf(hr[j], reW2[j * 16 + c], a));
        g_eattr[e * 16 + c] = a;
    }
}

// ---------------- conv layer: per-edge weight MLP + tensor product + scatter ----------------
// fc2 weight smem layout (per k row of 416):
//   [0,384): 6 column-pairs interleaved: dest = j*64 + lane*2 + s  <=  src col i=2j+s, lane
//   [384,416): scalar block i=12 at original position
__global__ void __launch_bounds__(cfg::CONV_THREADS, 1)
conv_kernel(const int* __restrict__ ei,
            const float* __restrict__ W1g, const float* __restrict__ B1g,
            const float* __restrict__ W2g, const float* __restrict__ B2g) {
    extern __shared__ float smem[];
    float* sW1 = smem;               // [48][64]
    float* sB1 = sW1 + 3072;         // [64]
    float* sW2 = sB1 + 64;           // [64][416] permuted
    float* sB2 = sW2 + 26624;        // [416]
    float* sWS = sB2 + 416;

    for (int t = threadIdx.x; t < 3072; t += blockDim.x) sW1[t] = W1g[t];
    for (int t = threadIdx.x; t < 64; t += blockDim.x) sB1[t] = B1g[t];
    for (int t = threadIdx.x; t < 26624; t += blockDim.x) {
        int k = t / 416, p = t - k * 416;
        int dest;
        if (p < 384) {
            int i = p >> 5, l = p & 31;
            dest = k * 416 + (i >> 1) * 64 + l * 2 + (i & 1);
        } else {
            dest = t;
        }
        sW2[dest] = W2g[t];
    }
    for (int t = threadIdx.x; t < 416; t += blockDim.x) sB2[t] = B2g[t];
    __syncthreads();

    const int lane = threadIdx.x & 31;
    const int warp = threadIdx.x >> 5;
    float* ws    = sWS + warp * cfg::WS;
    float* s_ea  = ws;          // [48][8] interleaved: s_ea[c*8+e]
    float* s_h   = ws + 384;    // [64][8] interleaved: s_h[k*8+e]
    float* s_x1  = ws + 896;    // [8][4][3]
    float* s_y1  = ws + 992;    // [8][3]
    float* s_dot = ws + 1016;   // [8][4]
    float* s_cr  = ws + 1048;   // [8][4][3]
    int*   s_idx = (int*)(ws + 1144); // [16]: src 0..7, dst 8..15

    const unsigned FULL = 0xffffffffu;
    const int numGroups = cfg::NE / cfg::EPG;   // 16000
    const int warpsTotal = gridDim.x * cfg::NWARP;

    for (int g = blockIdx.x * cfg::NWARP + warp; g < numGroups; g += warpsTotal) {
        const int ebase = g * cfg::EPG;

        // ---- phase 1: gather edge features (8 edges), interleaved layout ----
        if (lane < 8) s_idx[lane] = ei[ebase + lane];
        else if (lane < 16) s_idx[lane] = ei[cfg::NE + ebase + (lane - 8)];
        __syncwarp();
        #pragma unroll
        for (int j = 0; j < 12; j++) {
            int t = lane + 32 * j;          // 0..383
            int e = t / 48;
            int c = t - e * 48;
            float v;
            if (c < 16) {
                v = g_eattr[(ebase + e) * 16 + c];
            } else if (c < 32) {
                v = g_h0[s_idx[e] * 16 + (c - 16)];
            } else {
                v = g_h0[s_idx[8 + e] * 16 + (c - 32)];
            }
            s_ea[c * 8 + e] = v;
        }
        if (lane < 24) {
            int e = lane / 3, m = lane - e * 3;
            s_y1[lane] = g_y1[(ebase + e) * 3 + m];
        }
        {
            int e = lane >> 2, n = lane & 3;
            int dn = s_idx[8 + e];
            s_x1[e * 12 + n * 3 + 0] = g_h1[dn * 12 + n * 3 + 0];
            s_x1[e * 12 + n * 3 + 1] = g_h1[dn * 12 + n * 3 + 1];
            s_x1[e * 12 + n * 3 + 2] = g_h1[dn * 12 + n * 3 + 2];
        }
        __syncwarp();
        {
            int e = lane >> 2, n = lane & 3;
            float xa = s_x1[e * 12 + n * 3 + 0], xb = s_x1[e * 12 + n * 3 + 1], xc = s_x1[e * 12 + n * 3 + 2];
            float ya = s_y1[e * 3 + 0], yb = s_y1[e * 3 + 1], yc = s_y1[e * 3 + 2];
            s_dot[e * 4 + n] = (xa * ya + xb * yb + xc * yc) * 0.57735026918962576f;
            s_cr[e * 12 + n * 3 + 0] = (xb * yc - xc * yb) * 0.70710678118654752f;
            s_cr[e * 12 + n * 3 + 1] = (xc * ya - xa * yc) * 0.70710678118654752f;
            s_cr[e * 12 + n * 3 + 2] = (xa * yb - xb * ya) * 0.70710678118654752f;
        }
        __syncwarp();

        // ---- phase 2: fc1 (48 -> 64, relu), FFMA2 over edge pairs ----
        // lane owns hidden k = lane and lane+32; edge pairs p: (2p, 2p+1)
        {
            ull hacc[2][4];
            #pragma unroll
            for (int kk = 0; kk < 2; kk++) {
                float b = sB1[lane + 32 * kk];
                ull bb = pk2(b, b);
                #pragma unroll
                for (int p = 0; p < 4; p++) hacc[kk][p] = bb;
            }
            #pragma unroll 4
            for (int c = 0; c < 48; c++) {
                ull vp[4];
                #pragma unroll
                for (int p = 0; p < 4; p++)
                    vp[p] = *(const ull*)(s_ea + c * 8 + 2 * p);
                float w1a = sW1[c * 64 + lane];
                float w1b = sW1[c * 64 + lane + 32];
                ull wa2 = pk2(w1a, w1a), wb2 = pk2(w1b, w1b);
                #pragma unroll
                for (int p = 0; p < 4; p++) {
                    hacc[0][p] = ffma2(vp[p], wa2, hacc[0][p]);
                    hacc[1][p] = ffma2(vp[p], wb2, hacc[1][p]);
                }
            }
            #pragma unroll
            for (int kk = 0; kk < 2; kk++) {
                float* hrow = s_h + (lane + 32 * kk) * 8;
                #pragma unroll
                for (int p = 0; p < 4; p++) {
                    float2 f = upk2(hacc[kk][p]);
                    f.x = fmaxf(f.x, 0.f); f.y = fmaxf(f.y, 0.f);
                    *(float2*)(hrow + 2 * p) = f;
                }
            }
        }
        __syncwarp();

        // ---- phase 3: fc2 (64 -> 416), FFMA2 over output-column pairs ----
        // lane owns p = lane + 32*i; pairs j: (i=2j, i=2j+1); i=12 scalar
        ull acc[cfg::EPG][6];
        float accs[cfg::EPG];
        #pragma unroll
        for (int j = 0; j < 6; j++) {
            ull b2 = pk2(sB2[lane + 64 * j], sB2[lane + 64 * j + 32]);
            #pragma unroll
            for (int e = 0; e < cfg::EPG; e++) acc[e][j] = b2;
        }
        {
            float bs = sB2[384 + lane];
            #pragma unroll
            for (int e = 0; e < cfg::EPG; e++) accs[e] = bs;
        }
        #pragma unroll 2
        for (int k = 0; k < 64; k++) {
            const float* rw = sW2 + k * 416;
            ull w2p[6];
            #pragma unroll
            for (int j = 0; j < 6; j++)
                w2p[j] = *(const ull*)(rw + j * 64 + lane * 2);
            float w2s = rw[384 + lane];
            const float* hk = s_h + k * 8;
            #pragma unroll
            for (int e = 0; e < cfg::EPG; e++) {
                float h = hk[e];
                ull hh = pk2(h, h);
                #pragma unroll
                for (int j = 0; j < 6; j++)
                    acc[e][j] = ffma2(hh, w2p[j], acc[e][j]);
                accs[e] = fmaf(h, w2s, accs[e]);
            }
        }

        // ---- phase 4: tensor-product contraction via shuffle reductions + scatter ----
        // w layout: [0,256)=w00[n16,o16] [256,320)=w011[n16,o4] [320,336)=w101[n4,o4]
        //           [336,400)=w110[n4,o16] [400,416)=w111[n4,o4]
        #pragma unroll
        for (int e = 0; e < cfg::EPG; e++) {
            float w[13];
            #pragma unroll
            for (int j = 0; j < 6; j++) {
                float2 f = upk2(acc[e][j]);
                w[2 * j] = f.x; w[2 * j + 1] = f.y;
            }
            w[12] = accs[e];

            const float* x0p = s_ea + 32 * 8 + e;   // h0[dst], stride 8
            float ro0 = 0.f, rt = 0.f, r1a = 0.f, r1b = 0.f, r1c = 0.f;
            // w00: i=0..7, n = 2i + lane/16, o = lane&15; pairwise xor16 reduce
            #pragma unroll
            for (int i = 0; i < 8; i++) {
                int n = 2 * i + (lane >> 4);
                float c = w[i] * x0p[n * 8];
                ro0 += c + __shfl_xor_sync(FULL, c, 16);
            }
            // w011: i=8,9 -> t011[o = lane&3] via xor4/8/16
            #pragma unroll
            for (int i = 8; i < 10; i++) {
                int n = ((i - 8) * 32 + lane) >> 2;
                float c = w[i] * x0p[n * 8];
                c += __shfl_xor_sync(FULL, c, 4);
                c += __shfl_xor_sync(FULL, c, 8);
                c += __shfl_xor_sync(FULL, c, 16);
                rt += c;
            }
            {   // i=10: low lanes w101 (n=lane/4,o=lane&3), high lanes w110 (n=0,o=lane-16)
                float wv = w[10];
                float c = (lane >= 16) ? wv * s_dot[e * 4 + 0] : 0.f;
                ro0 += c + __shfl_xor_sync(FULL, c, 16);
                int n = (lane & 15) >> 2;
                const float* xp = s_x1 + e * 12 + n * 3;
                float m0 = (lane < 16) ? wv * xp[0] : 0.f;
                float m1 = (lane < 16) ? wv * xp[1] : 0.f;
                float m2 = (lane < 16) ? wv * xp[2] : 0.f;
                m0 += __shfl_xor_sync(FULL, m0, 4); m0 += __shfl_xor_sync(FULL, m0, 8);
                m1 += __shfl_xor_sync(FULL, m1, 4); m1 += __shfl_xor_sync(FULL, m1, 8);
                m2 += __shfl_xor_sync(FULL, m2, 4); m2 += __shfl_xor_sync(FULL, m2, 8);
                r1a += m0; r1b += m1; r1c += m2;
            }
            {   // i=11: all w110, n = 1 (low) / 2 (high), o = lane&15
                float c = w[11] * s_dot[e * 4 + ((lane < 16) ? 1 : 2)];
                ro0 += c + __shfl_xor_sync(FULL, c, 16);
            }
            {   // i=12: low lanes w110 (n=3,o=lane), high lanes w111 (n=(lane-16)/4,o=(lane-16)&3)
                float wv = w[12];
                float c = (lane < 16) ? wv * s_dot[e * 4 + 3] : 0.f;
                ro0 += c + __shfl_xor_sync(FULL, c, 16);
                int n = (lane & 15) >> 2;
                const float* cp = s_cr + e * 12 + n * 3;
                float m0 = (lane >= 16) ? wv * cp[0] : 0.f;
                float m1 = (lane >= 16) ? wv * cp[1] : 0.f;
                float m2 = (lane >= 16) ? wv * cp[2] : 0.f;
                m0 += __shfl_xor_sync(FULL, m0, 4); m0 += __shfl_xor_sync(FULL, m0, 8); m0 += __shfl_xor_sync(FULL, m0, 16);
                m1 += __shfl_xor_sync(FULL, m1, 4); m1 += __shfl_xor_sync(FULL, m1, 8); m1 += __shfl_xor_sync(FULL, m1, 16);
                m2 += __shfl_xor_sync(FULL, m2, 4); m2 += __shfl_xor_sync(FULL, m2, 8); m2 += __shfl_xor_sync(FULL, m2, 16);
                r1a += m0; r1b += m1; r1c += m2;
            }
            // t011[o] * y1[m]  (rt holds t011[lane&3] on every lane)
            r1a += rt * s_y1[e * 3 + 0];
            r1b += rt * s_y1[e * 3 + 1];
            r1c += rt * s_y1[e * 3 + 2];

            int sn = s_idx[e];
            if (lane < 16)
                atomicAdd(&g_acc0[sn * 16 + lane], 0.22360679774997896f * ro0);   // 1/sqrt(20)
            if (lane < 4) {
                atomicAdd(&g_acc1[sn * 12 + lane * 3 + 0], 0.20412414523193150f * r1a); // 1/sqrt(24)
                atomicAdd(&g_acc1[sn * 12 + lane * 3 + 1], 0.20412414523193150f * r1b);
                atomicAdd(&g_acc1[sn * 12 + lane * 3 + 2], 0.20412414523193150f * r1c);
            }
        }
        __syncwarp();
    }
}

// ---------------- scatter-mean residual update, zero accumulators ----------------
__global__ void update_kernel() {
    int i = blockIdx.x * blockDim.x + threadIdx.x;
    if (i < cfg::NN * 16) {
        int n = i >> 4;
        float inv = 1.f / fmaxf(g_cnt[n], 1.f);
        g_h0[i] += g_acc0[i] * inv;
        g_acc0[i] = 0.f;
    }
    if (i < cfg::NN * 12) {
        int n = i / 12;
        float inv = 1.f / fmaxf(g_cnt[n], 1.f);
        g_h1[i] += g_acc1[i] * inv;
        g_acc1[i] = 0.f;
    }
}

// ---------------- final update + o3.Linear + sorter layout ----------------
__global__ void final_kernel(float* __restrict__ out,
                             const float* __restrict__ lin0, const float* __restrict__ lin1) {
    int n = blockIdx.x * blockDim.x + threadIdx.x;
    if (n >= cfg::NN) return;
    float inv = 1.f / fmaxf(g_cnt[n], 1.f);
    float h0f[16];
    #pragma unroll
    for (int s = 0; s < 16; s++) h0f[s] = g_h0[n * 16 + s] + g_acc0[n * 16 + s] * inv;
    float h1f[12];
    #pragma unroll
    for (int s = 0; s < 12; s++) h1f[s] = g_h1[n * 12 + s] + g_acc1[n * 12 + s] * inv;
    float* o = out + (size_t)n * 128;
    #pragma unroll 4
    for (int c = 0; c < 32; c++) {
        float f0 = 0.f;
        #pragma unroll
        for (int s = 0; s < 16; s++) f0 = fmaf(h0f[s], lin0[s * 32 + c], f0);
        o[4 * c] = 0.25f * f0;                 // 1/sqrt(16)
        #pragma unroll
        for (int m = 0; m < 3; m++) {
            float f1 = 0.f;
            #pragma unroll
            for (int v = 0; v < 4; v++) f1 = fmaf(h1f[v * 3 + m], lin1[v * 32 + c], f1);
            o[4 * c + 1 + m] = 0.5f * f1;      // 1/sqrt(4)
        }
    }
}

// ---------------- launch ----------------
extern "C" void kernel_launch(void* const* d_in, const int* in_sizes, int n_in,
                              void* d_out, int out_size) {
    const float* pos          = (const float*)d_in[0];
    const float* node_feats   = (const float*)d_in[1];
    const float* edge_attr_in = (const float*)d_in[2];
    const int*   edge_index   = (const int*)d_in[3];
    const float* enc_W  = (const float*)d_in[4];
    const float* enc_b  = (const float*)d_in[5];
    const float* ne_W1  = (const float*)d_in[6];
    const float* ne_b1  = (const float*)d_in[7];
    const float* ne_W2  = (const float*)d_in[8];
    const float* ne_b2  = (const float*)d_in[9];
    const float* ee_W1  = (const float*)d_in[10];
    const float* ee_b1  = (const float*)d_in[11];
    const float* ee_W2  = (const float*)d_in[12];
    const float* ee_b2  = (const float*)d_in[13];
    const float* re_W1  = (const float*)d_in[14];
    const float* re_b1  = (const float*)d_in[15];
    const float* re_W2  = (const float*)d_in[16];
    const float* re_b2  = (const float*)d_in[17];
    const float* fc1_W  = (const float*)d_in[18];   // [2,48,64]
    const float* fc1_b  = (const float*)d_in[19];   // [2,64]
    const float* fc2_W  = (const float*)d_in[20];   // [2,64,416]
    const float* fc2_b  = (const float*)d_in[21];   // [2,416]
    const float* lin0_W = (const float*)d_in[22];
    const float* lin1_W = (const float*)d_in[23];
    float* out = (float*)d_out;

    int dev = 0;
    cudaGetDevice(&dev);
    int nsm = 148;
    cudaDeviceGetAttribute(&nsm, cudaDevAttrMultiProcessorCount, dev);
    cudaFuncSetAttribute(conv_kernel, cudaFuncAttributeMaxDynamicSharedMemorySize, cfg::SMEM_BYTES);

    zero_kernel<<<256, 256>>>();
    node_init_kernel<<<(cfg::NN + 127) / 128, 128>>>(node_feats, enc_W, enc_b,
                                                     ne_W1, ne_b1, ne_W2, ne_b2);
    edge_init_kernel<<<(cfg::NE + 127) / 128, 128>>>(pos, edge_attr_in, edge_index,
                                                     ee_W1, ee_b1, ee_W2, ee_b2,
                                                     re_W1, re_b1, re_W2, re_b2);
    // layer 0
    conv_kernel<<<nsm, cfg::CONV_THREADS, cfg::SMEM_BYTES>>>(edge_index,
        fc1_W, fc1_b, fc2_W, fc2_b);
    update_kernel<<<(cfg::NN * 16 + 255) / 256, 256>>>();
    // layer 1
    conv_kernel<<<nsm, cfg::CONV_THREADS, cfg::SMEM_BYTES>>>(edge_index,
        fc1_W + 48 * 64, fc1_b + 64, fc2_W + 64 * 416, fc2_b + 416);
    // final update + output projection
    final_kernel<<<(cfg::NN + 127) / 128, 128>>>(out, lin0_W, lin1_W);
}